// round 8
// baseline (speedup 1.0000x reference)
#include <cuda_runtime.h>
#include <cuda_bf16.h>
#include <math.h>
#include <stdint.h>

#define NB 2
#define NT 4096
#define ND 1024
#define DH 32
#define KTOP 8
#define TILE 128
#define KC 32            // bf16 K-chunk: 32 elems = 64 bytes/row
#define NCH (ND / KC)    // 32 chunks
#define NCPT 12          // candidates kept per tile (screening margin)
#define NCAND 12         // merged candidates per row

// ---------------- scratch (device globals; no allocation) ----------------
__device__ __nv_bfloat16 g_xb[NB * NT * ND];
__device__ float g_q[NB * NT * DH];
__device__ float g_k[NB * NT * DH];
__device__ float g_cv[NB * NT * 32 * NCPT];
__device__ int   g_ci[NB * NT * 32 * NCPT];
__device__ int   g_cand[NB * NT * NCAND];
__device__ int   g_cnt[NB * NT];
__device__ float g_meanp[128 * ND];
__device__ float g_mean[NB * ND];

// ======================= helpers ===========================
__device__ __forceinline__ uint32_t smem_u32(const void* p) {
    uint32_t a;
    asm("{ .reg .u64 t; cvta.to.shared.u64 t, %1; cvt.u32.u64 %0, t; }" : "=r"(a) : "l"(p));
    return a;
}
#define SW64(o) ((o) ^ (((o) >> 3) & 0x30))
#define CP_ASYNC16(dst, src) \
    asm volatile("cp.async.cg.shared.global [%0], [%1], 16;" :: "r"(dst), "l"(src))
#define CP_COMMIT() asm volatile("cp.async.commit_group;" ::: "memory")
#define CP_WAIT(n)  asm volatile("cp.async.wait_group %0;" :: "n"(n) : "memory")

__device__ __forceinline__ void ldmatrix_x4(uint32_t& r0, uint32_t& r1, uint32_t& r2, uint32_t& r3,
                                            uint32_t addr) {
    asm volatile("ldmatrix.sync.aligned.m8n8.x4.shared.b16 {%0,%1,%2,%3}, [%4];"
                 : "=r"(r0), "=r"(r1), "=r"(r2), "=r"(r3) : "r"(addr));
}
__device__ __forceinline__ void mma_bf16(float& c0, float& c1, float& c2, float& c3,
                                         uint32_t a0, uint32_t a1, uint32_t a2, uint32_t a3,
                                         uint32_t b0, uint32_t b1) {
    asm volatile("mma.sync.aligned.m16n8k16.row.col.f32.bf16.bf16.f32 "
                 "{%0,%1,%2,%3}, {%4,%5,%6,%7}, {%8,%9}, {%0,%1,%2,%3};"
                 : "+f"(c0), "+f"(c1), "+f"(c2), "+f"(c3)
                 : "r"(a0), "r"(a1), "r"(a2), "r"(a3), "r"(b0), "r"(b1));
}

// ========= Kernel: fused prologue (qk projection + x->bf16 + mean partials) =========
// 128 blocks x 64 rows, 256 threads.
__global__ __launch_bounds__(256) void prep_kernel(const float* __restrict__ x,
                                                   const float* __restrict__ Wq,
                                                   const float* __restrict__ Wk)
{
    const int row0 = blockIdx.x * 64;
    __shared__ float xs[16][64];
    __shared__ float ws[16][64];
    const int tid = threadIdx.x;
    const int ty = tid >> 4, tx = tid & 15;
    const int lr = tid >> 2;
    const int lk = (tid & 3) * 4;
    float acc[4][4];
#pragma unroll
    for (int i = 0; i < 4; ++i)
#pragma unroll
        for (int j = 0; j < 4; ++j) acc[i][j] = 0.0f;

    const float* Wrow = (lr < 32) ? (Wq + (size_t)lr * ND) : (Wk + (size_t)(lr - 32) * ND);
    for (int kd = 0; kd < ND; kd += 16) {
        const float4 xv = *(const float4*)(x + (size_t)(row0 + lr) * ND + kd + lk);
        const float4 wv = *(const float4*)(Wrow + kd + lk);
        __syncthreads();
        xs[lk + 0][lr] = xv.x; xs[lk + 1][lr] = xv.y; xs[lk + 2][lr] = xv.z; xs[lk + 3][lr] = xv.w;
        ws[lk + 0][lr] = wv.x; ws[lk + 1][lr] = wv.y; ws[lk + 2][lr] = wv.z; ws[lk + 3][lr] = wv.w;
        __syncthreads();
#pragma unroll
        for (int k = 0; k < 16; ++k) {
            const float4 a  = *(const float4*)&xs[k][4 * ty];
            const float4 w4 = *(const float4*)&ws[k][4 * tx];
            const float ar[4] = {a.x, a.y, a.z, a.w};
            const float br[4] = {w4.x, w4.y, w4.z, w4.w};
#pragma unroll
            for (int i = 0; i < 4; ++i)
#pragma unroll
                for (int j = 0; j < 4; ++j)
                    acc[i][j] = fmaf(ar[i], br[j], acc[i][j]);
        }
    }
#pragma unroll
    for (int i = 0; i < 4; ++i) {
        const int rw = row0 + 4 * ty + i;
#pragma unroll
        for (int j = 0; j < 4; ++j) {
            const int h = 4 * tx + j;
            if (h < 32) g_q[(size_t)rw * DH + h] = acc[i][j];
            else        g_k[(size_t)rw * DH + (h - 32)] = acc[i][j];
        }
    }

    // ---- x -> bf16 for this block's 64 rows ----
    const float4* xs4 = (const float4*)(x + (size_t)row0 * ND);
    __nv_bfloat162* ob = (__nv_bfloat162*)(g_xb + (size_t)row0 * ND);
#pragma unroll 4
    for (int i = tid; i < 64 * 256; i += 256) {
        const float4 v = xs4[i];
        ob[2 * i + 0] = __floats2bfloat162_rn(v.x, v.y);
        ob[2 * i + 1] = __floats2bfloat162_rn(v.z, v.w);
    }

    // ---- fp32 column partial sums over this block's 64 rows ----
    float4 macc = {0.f, 0.f, 0.f, 0.f};
    const float* xr = x + (size_t)row0 * ND + 4 * tid;
#pragma unroll 4
    for (int rr = 0; rr < 64; ++rr) {
        const float4 v = *(const float4*)(xr + (size_t)rr * ND);
        macc.x += v.x; macc.y += v.y; macc.z += v.z; macc.w += v.w;
    }
    *(float4*)(g_meanp + (size_t)blockIdx.x * ND + 4 * tid) = macc;
}

// =============== Kernel: HMMA sim GEMM + per-tile top-12 =============
// One CTA per (tt, jt) pair per batch. 256 threads = 8 warps (2m x 4n),
// warp tile 64x32, mma m16n8k16 bf16, fp32 accum.
// cp.async 3-stage pipeline; 2 CTAs/SM.
__global__ __launch_bounds__(256, 2) void simmma_kernel()
{
    __shared__ __align__(128) char sm[49152];   // 3 stages x (A 8KB | B 8KB); reused for scores
    const int tid = threadIdx.x;
    const int w = tid >> 5, l = tid & 31;
    const int b = blockIdx.y;

    // decode job -> (tt, jt)
    const int id = blockIdx.x;
    int tt = (int)((sqrtf(8.0f * (float)id + 1.0f) - 1.0f) * 0.5f);
    while ((tt + 1) * (tt + 2) / 2 <= id) ++tt;
    while (tt * (tt + 1) / 2 > id) --tt;
    const int jt = id - tt * (tt + 1) / 2;
    const int t0 = tt * TILE, j0 = jt * TILE;

    const int wm = (w >> 2) * 64;     // warp row offset (0 or 64)
    const int wn = (w & 3) * 32;      // warp col offset

    // ---- precompute swizzled ldmatrix byte offsets (within 8KB region) ----
    const int lr8 = l & 7;
    const int lb3 = (l >> 3) & 1;
    const int lb4 = (l >> 4) & 1;
    uint32_t aoff[4], boff[2];
#pragma unroll
    for (int mi = 0; mi < 4; ++mi) {
        const uint32_t row = (uint32_t)(wm + mi * 16 + lr8 + lb3 * 8);
        aoff[mi] = SW64(row * 64 + (uint32_t)lb4 * 16);
    }
#pragma unroll
    for (int n2 = 0; n2 < 2; ++n2) {
        const uint32_t row = (uint32_t)(wn + n2 * 16 + lb4 * 8 + lr8);
        boff[n2] = SW64(row * 64 + (uint32_t)lb3 * 16);
    }

    float acc[4][4][4];
#pragma unroll
    for (int mi = 0; mi < 4; ++mi)
#pragma unroll
        for (int ni = 0; ni < 4; ++ni)
#pragma unroll
            for (int q = 0; q < 4; ++q) acc[mi][ni][q] = 0.0f;

    const __nv_bfloat16* xb = g_xb + (size_t)b * NT * ND;
    const int r  = tid >> 1;              // row 0..127
    const int u0 = (tid & 1) * 2;         // first 16B unit within 64B row
    const uint32_t sb = smem_u32(sm);
    const uint32_t so0 = SW64((uint32_t)(r * 64 + u0 * 16));
    const uint32_t so1 = SW64((uint32_t)(r * 64 + (u0 + 1) * 16));
    const __nv_bfloat16* arow = xb + (size_t)(t0 + r) * ND + u0 * 8;
    const __nv_bfloat16* brow = xb + (size_t)(j0 + r) * ND + u0 * 8;

#define ISSUE(cc, pp) do {                                                      \
    const uint32_t aB_ = sb + (pp) * 16384;                                     \
    const __nv_bfloat16* as_ = arow + (cc) * KC;                                \
    const __nv_bfloat16* bs_ = brow + (cc) * KC;                                \
    CP_ASYNC16(aB_ + so0, as_);        CP_ASYNC16(aB_ + so1, as_ + 8);          \
    CP_ASYNC16(aB_ + 8192 + so0, bs_); CP_ASYNC16(aB_ + 8192 + so1, bs_ + 8);   \
    CP_COMMIT();                                                                \
} while (0)

    ISSUE(0, 0);
    ISSUE(1, 1);
#pragma unroll 1
    for (int c = 0; c < NCH; ++c) {
        const int p = c % 3;
        if (c + 1 < NCH) CP_WAIT(1); else CP_WAIT(0);
        __syncthreads();
        if (c + 2 < NCH) ISSUE(c + 2, (c + 2) % 3);
        const uint32_t aB = sb + p * 16384;
        const uint32_t bB = aB + 8192;
#pragma unroll
        for (int ks = 0; ks < 2; ++ks) {
            uint32_t af[4][4], bf[2][4];
#pragma unroll
            for (int mi = 0; mi < 4; ++mi)
                ldmatrix_x4(af[mi][0], af[mi][1], af[mi][2], af[mi][3],
                            aB + (aoff[mi] ^ (ks * 32)));
#pragma unroll
            for (int n2 = 0; n2 < 2; ++n2)
                ldmatrix_x4(bf[n2][0], bf[n2][1], bf[n2][2], bf[n2][3],
                            bB + (boff[n2] ^ (ks * 32)));
#pragma unroll
            for (int mi = 0; mi < 4; ++mi)
#pragma unroll
                for (int ni = 0; ni < 4; ++ni)
                    mma_bf16(acc[mi][ni][0], acc[mi][ni][1], acc[mi][ni][2], acc[mi][ni][3],
                             af[mi][0], af[mi][1], af[mi][2], af[mi][3],
                             bf[ni >> 1][(ni & 1) * 2], bf[ni >> 1][(ni & 1) * 2 + 1]);
        }
    }
#undef ISSUE

    // ---- epilogue: 2 phases x 64 cols; 2 threads/row (32+32 cols each) ----
    const int g  = l >> 2;
    const int tg = l & 3;
    float* sc = (float*)sm;                 // [128][68] per phase (34816 B)
    const int row  = tid & 127;
    const int half = tid >> 7;
    const int myt  = t0 + row;
    float tv[NCPT]; int tj[NCPT];
#pragma unroll
    for (int i = 0; i < NCPT; ++i) { tv[i] = -3.0e38f; tj[i] = 0; }

#pragma unroll 1
    for (int ph = 0; ph < 2; ++ph) {
        __syncthreads();                    // prior reads done
        if (((w & 3) >> 1) == ph) {
            const int cb = ((w & 3) & 1) * 32;
#pragma unroll
            for (int mi = 0; mi < 4; ++mi)
#pragma unroll
                for (int ni = 0; ni < 4; ++ni) {
                    const int colw = cb + ni * 8 + tg * 2;
                    float* p0 = sc + (wm + mi * 16 + g) * 68 + colw;
                    float* p1 = sc + (wm + mi * 16 + g + 8) * 68 + colw;
                    p0[0] = acc[mi][ni][0]; p0[1] = acc[mi][ni][1];
                    p1[0] = acc[mi][ni][2]; p1[1] = acc[mi][ni][3];
                }
        }
        __syncthreads();
        {
            const float4* rowp = (const float4*)(sc + row * 68) + half * 8;
            const int jb = j0 + ph * 64 + half * 32;
            float thr = tv[NCPT - 1];
#pragma unroll 1
            for (int v4 = 0; v4 < 8; ++v4) {
                const float4 vv = rowp[v4];
                const float m01 = fmaxf(vv.x, vv.y);
                const float m23 = fmaxf(vv.z, vv.w);
                if (fmaxf(m01, m23) > thr) {
                    const int jb4 = jb + v4 * 4;
                    const float va[4] = {vv.x, vv.y, vv.z, vv.w};
#pragma unroll
                    for (int e = 0; e < 4; ++e) {
                        const float v = va[e];
                        const int   j = jb4 + e;
                        if (v > thr && j < myt) {
                            tv[NCPT - 1] = v; tj[NCPT - 1] = j;
#pragma unroll
                            for (int q = NCPT - 1; q > 0; --q) {
                                if (tv[q] > tv[q - 1]) {
                                    const float tf = tv[q]; tv[q] = tv[q - 1]; tv[q - 1] = tf;
                                    const int   ii = tj[q]; tj[q] = tj[q - 1]; tj[q - 1] = ii;
                                }
                            }
                            thr = tv[NCPT - 1];
                        }
                    }
                }
            }
        }
    }

    // merge the two half-lists per row (high half -> smem, low half merges)
    __syncthreads();
    float* mv  = sc;                        // [128][NCPT]
    int*   mi2 = (int*)(sc + 128 * NCPT);   // [128][NCPT]
    if (half == 1) {
#pragma unroll
        for (int i = 0; i < NCPT; ++i) { mv[row * NCPT + i] = tv[i]; mi2[row * NCPT + i] = tj[i]; }
    }
    __syncthreads();
    if (half == 0) {
#pragma unroll 1
        for (int i = 0; i < NCPT; ++i) {
            const float v = mv[row * NCPT + i];
            if (v <= tv[NCPT - 1]) break;   // high list sorted desc
            const int j = mi2[row * NCPT + i];
            int pos = NCPT - 1;
            while (pos > 0 && tv[pos - 1] < v) {
                tv[pos] = tv[pos - 1]; tj[pos] = tj[pos - 1]; --pos;
            }
            tv[pos] = v; tj[pos] = j;
        }
        const size_t base = ((size_t)(b * NT + myt) * 32 + jt) * NCPT;
#pragma unroll
        for (int i = 0; i < NCPT; ++i) { g_cv[base + i] = tv[i]; g_ci[base + i] = tj[i]; }
    }
}

// ==== Kernel: merge per-tile lists -> top-12 candidates; + mean reduce ====
__global__ void merge_kernel()
{
    const int row = blockIdx.x * blockDim.x + threadIdx.x;
    if (row < NB * ND) {        // final mean reduction (2048 entries)
        const int b = row / ND, d = row % ND;
        float s = 0.0f;
        for (int z = 0; z < 64; ++z) s += g_meanp[(size_t)(b * 64 + z) * ND + d];
        g_mean[row] = s * (1.0f / (float)NT);
    }
    if (row >= NB * NT) return;
    const int t  = row & (NT - 1);
    const int nl = (t >> 7) + 1;
    float bv[NCAND]; int bi[NCAND];
    for (int i = 0; i < NCAND; ++i) { bv[i] = -3.0e38f; bi[i] = 0; }
    for (int l = 0; l < nl; ++l) {
        const size_t base = ((size_t)row * 32 + l) * NCPT;
        for (int i = 0; i < NCPT; ++i) {
            const float v = g_cv[base + i];
            if (v <= bv[NCAND - 1]) break;          // lists sorted desc
            const int j = g_ci[base + i];
            int pos = NCAND - 1;
            while (pos > 0 && bv[pos - 1] < v) {
                bv[pos] = bv[pos - 1]; bi[pos] = bi[pos - 1]; --pos;
            }
            bv[pos] = v; bi[pos] = j;
        }
    }
    int m = 0;
    for (int i = 0; i < NCAND; ++i) {
        if (bv[i] > -1.0e30f) { g_cand[(size_t)row * NCAND + i] = bi[i]; ++m; }
    }
    g_cnt[row] = m;
}

// ====== Kernel: fused exact fp32 re-rank + scores/softmax/msg/GELU ======
// One block (256 threads) per row.
__global__ __launch_bounds__(256) void finish_kernel(const float* __restrict__ x,
                                                     const float* __restrict__ gain,
                                                     const float* __restrict__ bias,
                                                     const float* __restrict__ p_lm,
                                                     const float* __restrict__ p_ls,
                                                     float* __restrict__ out)
{
    const int row = blockIdx.x;
    const int b = row >> 12;
    const int t = row & (NT - 1);
    const int tid = threadIdx.x, wid = tid >> 5, lane = tid & 31;

    const float mix   = 1.0f / (1.0f + expf(-p_lm[0]));
    const float scale = log1pf(expf(p_ls[0])) + 0.01f;

    __shared__ float sval[NCAND];
    __shared__ int   scand[NCAND];
    __shared__ float w8[KTOP];
    __shared__ int   jj[KTOP];

    const int m  = g_cnt[row];
    const int kk = m < KTOP ? m : KTOP;

    if (m > 0) {
        if (tid < m) scand[tid] = g_cand[(size_t)row * NCAND + tid];
        __syncthreads();

        // exact fp32 sim re-rank: one warp per candidate
        const float4* qa = (const float4*)(x + (size_t)(b * NT + t) * ND);
#pragma unroll 1
        for (int cc = wid; cc < m; cc += 8) {
            const int j = scand[cc];
            const float4* ka = (const float4*)(x + (size_t)(b * NT + j) * ND);
            float s = 0.0f;
#pragma unroll
            for (int i = 0; i < 8; ++i) {
                const float4 q4 = qa[i * 32 + lane];
                const float4 k4 = ka[i * 32 + lane];
                s = fmaf(q4.x, k4.x, s); s = fmaf(q4.y, k4.y, s);
                s = fmaf(q4.z, k4.z, s); s = fmaf(q4.w, k4.w, s);
            }
#pragma unroll
            for (int o = 16; o > 0; o >>= 1) s += __shfl_xor_sync(0xffffffffu, s, o);
            if (lane == 0) sval[cc] = s;
        }
        __syncthreads();
        if (tid == 0) {
            bool usedf[NCAND];
            for (int i = 0; i < m; ++i) usedf[i] = false;
            for (int rr = 0; rr < kk; ++rr) {
                int best = -1; float bvv = -3.4e38f;
                for (int i = 0; i < m; ++i)
                    if (!usedf[i] && sval[i] > bvv) { bvv = sval[i]; best = i; }
                usedf[best] = true;
                jj[rr] = scand[best];
            }
        }
        __syncthreads();

        // attention scores on the top-kk neighbors
        if (tid < kk) {
            const int j = jj[tid];
            const float* qv = g_q + (size_t)row * DH;
            const float* kv = g_k + ((size_t)b * NT + j) * DH;
            float sc = 0.0f;
#pragma unroll
            for (int h = 0; h < DH; ++h) sc = fmaf(qv[h], kv[h], sc);
            w8[tid] = sc * 0.17677669529663687f;   // 1/sqrt(32)
        }
        __syncthreads();
        if (tid == 0) {
            float mx = w8[0];
            for (int i = 1; i < kk; ++i) mx = fmaxf(mx, w8[i]);
            float sum = 0.0f;
            for (int i = 0; i < kk; ++i) { const float e = expf(w8[i] - mx); w8[i] = e; sum += e; }
            const float inv = 1.0f / sum;
            for (int i = 0; i < kk; ++i) w8[i] *= inv;
        }
        __syncthreads();
    }

    const int d0 = 4 * tid;
    float4 msg;
    if (m > 0) {
        float4 a = {0.f, 0.f, 0.f, 0.f};
        for (int i = 0; i < kk; ++i) {
            const float wi = w8[i];
            const float4 xv = *(const float4*)(x + ((size_t)b * NT + jj[i]) * ND + d0);
            a.x = fmaf(wi, xv.x, a.x);
            a.y = fmaf(wi, xv.y, a.y);
            a.z = fmaf(wi, xv.z, a.z);
            a.w = fmaf(wi, xv.w, a.w);
        }
        msg = a;
    } else {
        msg = *(const float4*)(g_mean + b * ND + d0);   // t==0: uniform over all T
    }

    const float4 xt = *(const float4*)(x + (size_t)row * ND + d0);
    const float4 gn = *(const float4*)(gain + d0);
    const float4 bs = *(const float4*)(bias + d0);
    const float om = 1.0f - mix;
    float4 o;
#define GEL(c) { float z = mix * xt.c + om * msg.c;                         \
                 z = fmaf(z, gn.c, bs.c);                                   \
                 o.c = 0.5f * z * (1.0f + erff(z * 0.7071067811865476f)) * scale; }
    GEL(x) GEL(y) GEL(z) GEL(w)
#undef GEL
    *(float4*)(out + (size_t)row * ND + d0) = o;
}

// =========================================================================
extern "C" void kernel_launch(void* const* d_in, const int* in_sizes, int n_in,
                              void* d_out, int out_size)
{
    (void)in_sizes; (void)n_in; (void)out_size;
    const float* x    = (const float*)d_in[0];
    const float* Wq   = (const float*)d_in[1];
    const float* Wk   = (const float*)d_in[2];
    const float* gain = (const float*)d_in[3];
    const float* bias = (const float*)d_in[4];
    const float* lm   = (const float*)d_in[5];
    const float* ls   = (const float*)d_in[6];
    float* out = (float*)d_out;

    prep_kernel<<<128, 256>>>(x, Wq, Wk);
    simmma_kernel<<<dim3(528, NB), 256>>>();
    merge_kernel<<<(NB * NT + 255) / 256, 256>>>();
    finish_kernel<<<NB * NT, 256>>>(x, gain, bias, lm, ls, out);
}

// round 10
// speedup vs baseline: 1.4416x; 1.4416x over previous
#include <cuda_runtime.h>
#include <cuda_bf16.h>
#include <math.h>
#include <stdint.h>

#define NB 2
#define NT 4096
#define ND 1024
#define DH 32
#define KTOP 8
#define TILE 128
#define KC 32            // bf16 K-chunk: 32 elems = 64 bytes/row
#define NCH (ND / KC)    // 32 chunks
#define NCPT 12          // candidates kept per tile (screening margin)
#define NCAND 12         // merged candidates per row

// ---------------- scratch (device globals; no allocation) ----------------
__device__ __nv_bfloat16 g_xb[NB * NT * ND];
__device__ float g_q[NB * NT * DH];
__device__ float g_k[NB * NT * DH];
__device__ float g_cv[NB * NT * 32 * NCPT];
__device__ int   g_ci[NB * NT * 32 * NCPT];
__device__ int   g_cand[NB * NT * NCAND];
__device__ int   g_cnt[NB * NT];
__device__ float g_meanp[16 * NB * ND];
__device__ float g_mean[NB * ND];

// ======================= helpers ===========================
__device__ __forceinline__ uint32_t smem_u32(const void* p) {
    uint32_t a;
    asm("{ .reg .u64 t; cvta.to.shared.u64 t, %1; cvt.u32.u64 %0, t; }" : "=r"(a) : "l"(p));
    return a;
}
#define SW64(o) ((o) ^ (((o) >> 3) & 0x30))
#define CP_ASYNC16(dst, src) \
    asm volatile("cp.async.cg.shared.global [%0], [%1], 16;" :: "r"(dst), "l"(src))
#define CP_COMMIT() asm volatile("cp.async.commit_group;" ::: "memory")
#define CP_WAIT(n)  asm volatile("cp.async.wait_group %0;" :: "n"(n) : "memory")

__device__ __forceinline__ void ldmatrix_x4(uint32_t& r0, uint32_t& r1, uint32_t& r2, uint32_t& r3,
                                            uint32_t addr) {
    asm volatile("ldmatrix.sync.aligned.m8n8.x4.shared.b16 {%0,%1,%2,%3}, [%4];"
                 : "=r"(r0), "=r"(r1), "=r"(r2), "=r"(r3) : "r"(addr));
}
__device__ __forceinline__ void mma_bf16(float& c0, float& c1, float& c2, float& c3,
                                         uint32_t a0, uint32_t a1, uint32_t a2, uint32_t a3,
                                         uint32_t b0, uint32_t b1) {
    asm volatile("mma.sync.aligned.m16n8k16.row.col.f32.bf16.bf16.f32 "
                 "{%0,%1,%2,%3}, {%4,%5,%6,%7}, {%8,%9}, {%0,%1,%2,%3};"
                 : "+f"(c0), "+f"(c1), "+f"(c2), "+f"(c3)
                 : "r"(a0), "r"(a1), "r"(a2), "r"(a3), "r"(b0), "r"(b1));
}

// ========================= Kernel: x -> bf16 ============================
__global__ __launch_bounds__(256) void xcvt_kernel(const float* __restrict__ x)
{
    const size_t i = (size_t)blockIdx.x * 256 + threadIdx.x;   // float4 index
    const float4 v = ((const float4*)x)[i];
    __nv_bfloat162* o = (__nv_bfloat162*)g_xb;
    o[2 * i + 0] = __floats2bfloat162_rn(v.x, v.y);
    o[2 * i + 1] = __floats2bfloat162_rn(v.z, v.w);
}

// =============== Kernel: HMMA sim GEMM + per-tile top-12 =============
// One CTA per (tt, jt) pair per batch. 256 threads = 8 warps (2m x 4n),
// warp tile 64x32, mma m16n8k16 bf16, fp32 accum.
// cp.async 3-stage pipeline; 2 CTAs/SM.
__global__ __launch_bounds__(256, 2) void simmma_kernel()
{
    __shared__ __align__(128) char sm[49152];   // 3 stages x (A 8KB | B 8KB); reused for scores
    const int tid = threadIdx.x;
    const int w = tid >> 5, l = tid & 31;
    const int b = blockIdx.y;

    // decode job -> (tt, jt)
    const int id = blockIdx.x;
    int tt = (int)((sqrtf(8.0f * (float)id + 1.0f) - 1.0f) * 0.5f);
    while ((tt + 1) * (tt + 2) / 2 <= id) ++tt;
    while (tt * (tt + 1) / 2 > id) --tt;
    const int jt = id - tt * (tt + 1) / 2;
    const int t0 = tt * TILE, j0 = jt * TILE;

    const int wm = (w >> 2) * 64;     // warp row offset (0 or 64)
    const int wn = (w & 3) * 32;      // warp col offset

    // ---- precompute swizzled ldmatrix byte offsets (within 8KB region) ----
    const int lr8 = l & 7;
    const int lb3 = (l >> 3) & 1;
    const int lb4 = (l >> 4) & 1;
    uint32_t aoff[4], boff[2];
#pragma unroll
    for (int mi = 0; mi < 4; ++mi) {
        const uint32_t row = (uint32_t)(wm + mi * 16 + lr8 + lb3 * 8);
        aoff[mi] = SW64(row * 64 + (uint32_t)lb4 * 16);
    }
#pragma unroll
    for (int n2 = 0; n2 < 2; ++n2) {
        const uint32_t row = (uint32_t)(wn + n2 * 16 + lb4 * 8 + lr8);
        boff[n2] = SW64(row * 64 + (uint32_t)lb3 * 16);
    }

    float acc[4][4][4];
#pragma unroll
    for (int mi = 0; mi < 4; ++mi)
#pragma unroll
        for (int ni = 0; ni < 4; ++ni)
#pragma unroll
            for (int q = 0; q < 4; ++q) acc[mi][ni][q] = 0.0f;

    const __nv_bfloat16* xb = g_xb + (size_t)b * NT * ND;
    const int r  = tid >> 1;              // row 0..127
    const int u0 = (tid & 1) * 2;         // first 16B unit within 64B row
    const uint32_t sb = smem_u32(sm);
    const uint32_t so0 = SW64((uint32_t)(r * 64 + u0 * 16));
    const uint32_t so1 = SW64((uint32_t)(r * 64 + (u0 + 1) * 16));
    const __nv_bfloat16* arow = xb + (size_t)(t0 + r) * ND + u0 * 8;
    const __nv_bfloat16* brow = xb + (size_t)(j0 + r) * ND + u0 * 8;

#define ISSUE(cc, pp) do {                                                      \
    const uint32_t aB_ = sb + (pp) * 16384;                                     \
    const __nv_bfloat16* as_ = arow + (cc) * KC;                                \
    const __nv_bfloat16* bs_ = brow + (cc) * KC;                                \
    CP_ASYNC16(aB_ + so0, as_);        CP_ASYNC16(aB_ + so1, as_ + 8);          \
    CP_ASYNC16(aB_ + 8192 + so0, bs_); CP_ASYNC16(aB_ + 8192 + so1, bs_ + 8);   \
    CP_COMMIT();                                                                \
} while (0)

    ISSUE(0, 0);
    ISSUE(1, 1);
#pragma unroll 1
    for (int c = 0; c < NCH; ++c) {
        const int p = c % 3;
        if (c + 1 < NCH) CP_WAIT(1); else CP_WAIT(0);
        __syncthreads();
        if (c + 2 < NCH) ISSUE(c + 2, (c + 2) % 3);
        const uint32_t aB = sb + p * 16384;
        const uint32_t bB = aB + 8192;
#pragma unroll
        for (int ks = 0; ks < 2; ++ks) {
            uint32_t af[4][4], bf[2][4];
#pragma unroll
            for (int mi = 0; mi < 4; ++mi)
                ldmatrix_x4(af[mi][0], af[mi][1], af[mi][2], af[mi][3],
                            aB + (aoff[mi] ^ (ks * 32)));
#pragma unroll
            for (int n2 = 0; n2 < 2; ++n2)
                ldmatrix_x4(bf[n2][0], bf[n2][1], bf[n2][2], bf[n2][3],
                            bB + (boff[n2] ^ (ks * 32)));
#pragma unroll
            for (int mi = 0; mi < 4; ++mi)
#pragma unroll
                for (int ni = 0; ni < 4; ++ni)
                    mma_bf16(acc[mi][ni][0], acc[mi][ni][1], acc[mi][ni][2], acc[mi][ni][3],
                             af[mi][0], af[mi][1], af[mi][2], af[mi][3],
                             bf[ni >> 1][(ni & 1) * 2], bf[ni >> 1][(ni & 1) * 2 + 1]);
        }
    }
#undef ISSUE

    // ---- epilogue: 2 phases x 64 cols; float4 scan with causal clamp ----
    const int g  = l >> 2;
    const int tg = l & 3;
    float* sc = (float*)sm;                 // [128][68] per phase (34816 B)
    float tv[NCPT]; int tj[NCPT];
#pragma unroll
    for (int i = 0; i < NCPT; ++i) { tv[i] = -3.0e38f; tj[i] = 0; }
    const int myt = t0 + tid;               // row this thread scans (tid < 128)

#pragma unroll 1
    for (int ph = 0; ph < 2; ++ph) {
        __syncthreads();                    // prior reads done
        if (((w & 3) >> 1) == ph) {
            const int cb = ((w & 3) & 1) * 32;
#pragma unroll
            for (int mi = 0; mi < 4; ++mi)
#pragma unroll
                for (int ni = 0; ni < 4; ++ni) {
                    const int colw = cb + ni * 8 + tg * 2;
                    float* p0 = sc + (wm + mi * 16 + g) * 68 + colw;
                    float* p1 = sc + (wm + mi * 16 + g + 8) * 68 + colw;
                    p0[0] = acc[mi][ni][0]; p0[1] = acc[mi][ni][1];
                    p1[0] = acc[mi][ni][2]; p1[1] = acc[mi][ni][3];
                }
        }
        __syncthreads();
        if (tid < 128) {
            const float4* rowp = (const float4*)(sc + tid * 68);
            const int jb = j0 + ph * 64;
            const int limit = myt - jb;     // columns [0, limit) are causal
            if (limit > 0) {
                const int nv4 = limit >= 64 ? 16 : ((limit + 3) >> 2);
                float thr = tv[NCPT - 1];
#pragma unroll 1
                for (int v4 = 0; v4 < nv4; ++v4) {
                    const float4 vv = rowp[v4];
                    const float m01 = fmaxf(vv.x, vv.y);
                    const float m23 = fmaxf(vv.z, vv.w);
                    if (fmaxf(m01, m23) > thr) {
                        const int jb4 = jb + v4 * 4;
                        const float va[4] = {vv.x, vv.y, vv.z, vv.w};
#pragma unroll
                        for (int e = 0; e < 4; ++e) {
                            const float v = va[e];
                            const int   j = jb4 + e;
                            if (v > thr && j < myt) {
                                tv[NCPT - 1] = v; tj[NCPT - 1] = j;
#pragma unroll
                                for (int q = NCPT - 1; q > 0; --q) {
                                    if (tv[q] > tv[q - 1]) {
                                        const float tf = tv[q]; tv[q] = tv[q - 1]; tv[q - 1] = tf;
                                        const int   ii = tj[q]; tj[q] = tj[q - 1]; tj[q - 1] = ii;
                                    }
                                }
                                thr = tv[NCPT - 1];
                            }
                        }
                    }
                }
            }
        }
    }

    if (tid < 128) {
        const size_t base = ((size_t)(b * NT + myt) * 32 + jt) * NCPT;
#pragma unroll
        for (int i = 0; i < NCPT; ++i) { g_cv[base + i] = tv[i]; g_ci[base + i] = tj[i]; }
    }
}

// ============ Kernel: merge per-tile lists -> top-12 candidates =========
__global__ void merge_kernel()
{
    const int row = blockIdx.x * blockDim.x + threadIdx.x;
    if (row >= NB * NT) return;
    const int t  = row & (NT - 1);
    const int nl = (t >> 7) + 1;
    float bv[NCAND]; int bi[NCAND];
    for (int i = 0; i < NCAND; ++i) { bv[i] = -3.0e38f; bi[i] = 0; }
    for (int l = 0; l < nl; ++l) {
        const size_t base = ((size_t)row * 32 + l) * NCPT;
        for (int i = 0; i < NCPT; ++i) {
            const float v = g_cv[base + i];
            if (v <= bv[NCAND - 1]) break;          // lists sorted desc
            const int j = g_ci[base + i];
            int pos = NCAND - 1;
            while (pos > 0 && bv[pos - 1] < v) {
                bv[pos] = bv[pos - 1]; bi[pos] = bi[pos - 1]; --pos;
            }
            bv[pos] = v; bi[pos] = j;
        }
    }
    int m = 0;
    for (int i = 0; i < NCAND; ++i) {
        if (bv[i] > -1.0e30f) { g_cand[(size_t)row * NCAND + i] = bi[i]; ++m; }
    }
    g_cnt[row] = m;
}

// ===================== Kernel: q/k projection ===========================
__global__ __launch_bounds__(256) void qk_kernel(const float* __restrict__ x,
                                                 const float* __restrict__ Wq,
                                                 const float* __restrict__ Wk)
{
    const int row0 = blockIdx.x * 64;
    __shared__ float xs[16][64];
    __shared__ float ws[16][64];
    const int tid = threadIdx.x;
    const int ty = tid >> 4, tx = tid & 15;
    const int lr = tid >> 2;
    const int lk = (tid & 3) * 4;
    float acc[4][4];
#pragma unroll
    for (int i = 0; i < 4; ++i)
#pragma unroll
        for (int j = 0; j < 4; ++j) acc[i][j] = 0.0f;

    const float* Wrow = (lr < 32) ? (Wq + (size_t)lr * ND) : (Wk + (size_t)(lr - 32) * ND);
    for (int kd = 0; kd < ND; kd += 16) {
        const float4 xv = *(const float4*)(x + (size_t)(row0 + lr) * ND + kd + lk);
        const float4 wv = *(const float4*)(Wrow + kd + lk);
        __syncthreads();
        xs[lk + 0][lr] = xv.x; xs[lk + 1][lr] = xv.y; xs[lk + 2][lr] = xv.z; xs[lk + 3][lr] = xv.w;
        ws[lk + 0][lr] = wv.x; ws[lk + 1][lr] = wv.y; ws[lk + 2][lr] = wv.z; ws[lk + 3][lr] = wv.w;
        __syncthreads();
#pragma unroll
        for (int k = 0; k < 16; ++k) {
            const float4 a  = *(const float4*)&xs[k][4 * ty];
            const float4 w4 = *(const float4*)&ws[k][4 * tx];
            const float ar[4] = {a.x, a.y, a.z, a.w};
            const float br[4] = {w4.x, w4.y, w4.z, w4.w};
#pragma unroll
            for (int i = 0; i < 4; ++i)
#pragma unroll
                for (int j = 0; j < 4; ++j)
                    acc[i][j] = fmaf(ar[i], br[j], acc[i][j]);
        }
    }
#pragma unroll
    for (int i = 0; i < 4; ++i) {
        const int rw = row0 + 4 * ty + i;
#pragma unroll
        for (int j = 0; j < 4; ++j) {
            const int h = 4 * tx + j;
            if (h < 32) g_q[(size_t)rw * DH + h] = acc[i][j];
            else        g_k[(size_t)rw * DH + (h - 32)] = acc[i][j];
        }
    }
}

// ============== Kernels: deterministic 2-pass column mean ===============
__global__ void mean1_kernel(const float* __restrict__ x)
{
    const int b = blockIdx.y, z = blockIdx.z;
    const int lane = threadIdx.x & 31, g = threadIdx.x >> 5;
    const int c4 = blockIdx.x * 32 + lane;
    const float* xb = x + (size_t)b * NT * ND;
    float4 acc = {0.f, 0.f, 0.f, 0.f};
    for (int r = z * 256 + g; r < z * 256 + 256; r += 8) {
        const float4 v = *(const float4*)(xb + (size_t)r * ND + 4 * c4);
        acc.x += v.x; acc.y += v.y; acc.z += v.z; acc.w += v.w;
    }
    __shared__ float4 red[8][32];
    red[g][lane] = acc;
    __syncthreads();
    if (g == 0) {
        float4 sm = red[0][lane];
        for (int q = 1; q < 8; ++q) {
            const float4 v = red[q][lane];
            sm.x += v.x; sm.y += v.y; sm.z += v.z; sm.w += v.w;
        }
        *(float4*)(g_meanp + ((size_t)z * NB + b) * ND + 4 * c4) = sm;
    }
}
__global__ void mean2_kernel()
{
    const int idx = blockIdx.x * blockDim.x + threadIdx.x;
    if (idx >= NB * ND) return;
    const int b = idx / ND, d = idx % ND;
    float s = 0.0f;
    for (int z = 0; z < 16; ++z) s += g_meanp[((size_t)z * NB + b) * ND + d];
    g_mean[b * ND + d] = s * (1.0f / (float)NT);
}

// ====== Kernel: fused exact fp32 re-rank + scores/softmax/msg/GELU ======
// One block (256 threads) per row. Sim dot and q.k dot computed in ONE
// warp-per-candidate pass; parallel rank selection (no serial sort).
__global__ __launch_bounds__(256) void finish_kernel(const float* __restrict__ x,
                                                     const float* __restrict__ gain,
                                                     const float* __restrict__ bias,
                                                     const float* __restrict__ p_lm,
                                                     const float* __restrict__ p_ls,
                                                     float* __restrict__ out)
{
    const int row = blockIdx.x;
    const int b = row >> 12;
    const int t = row & (NT - 1);
    const int tid = threadIdx.x, wid = tid >> 5, lane = tid & 31;

    const float mix   = 1.0f / (1.0f + expf(-p_lm[0]));
    const float scale = log1pf(expf(p_ls[0])) + 0.01f;

    // early, barrier-independent loads
    const int d0 = 4 * tid;
    const float4 xt = *(const float4*)(x + (size_t)row * ND + d0);
    const float4 gn = *(const float4*)(gain + d0);
    const float4 bs = *(const float4*)(bias + d0);

    __shared__ float sval[NCAND];
    __shared__ float sqk[NCAND];
    __shared__ int   scand[NCAND];
    __shared__ float w8[KTOP];
    __shared__ int   jj[KTOP];

    const int m  = g_cnt[row];
    const int kk = m < KTOP ? m : KTOP;

    if (m > 0) {
        if (tid < m) scand[tid] = g_cand[(size_t)row * NCAND + tid];
        __syncthreads();

        // one warp per candidate: exact fp32 sim dot (1024) + q.k dot (32)
        const float4* qa = (const float4*)(x + (size_t)(b * NT + t) * ND);
        const float qh = g_q[(size_t)row * DH + lane];
#pragma unroll 1
        for (int cc = wid; cc < m; cc += 8) {
            const int j = scand[cc];
            const float4* ka = (const float4*)(x + (size_t)(b * NT + j) * ND);
            float s = 0.0f;
#pragma unroll
            for (int i = 0; i < 8; ++i) {
                const float4 q4 = qa[i * 32 + lane];
                const float4 k4 = ka[i * 32 + lane];
                s = fmaf(q4.x, k4.x, s); s = fmaf(q4.y, k4.y, s);
                s = fmaf(q4.z, k4.z, s); s = fmaf(q4.w, k4.w, s);
            }
            float s2 = qh * g_k[((size_t)b * NT + j) * DH + lane];
#pragma unroll
            for (int o = 16; o > 0; o >>= 1) {
                s  += __shfl_xor_sync(0xffffffffu, s, o);
                s2 += __shfl_xor_sync(0xffffffffu, s2, o);
            }
            if (lane == 0) { sval[cc] = s; sqk[cc] = s2; }
        }
        __syncthreads();

        // parallel rank selection: rank = #{i: s_i > s || (s_i == s && i < tid)}
        if (tid < m) {
            const float v = sval[tid];
            int rank = 0;
#pragma unroll 1
            for (int i = 0; i < m; ++i) {
                const float u = sval[i];
                rank += (u > v) || (u == v && i < tid);
            }
            if (rank < kk) {
                jj[rank] = scand[tid];
                w8[rank] = sqk[tid] * 0.17677669529663687f;   // 1/sqrt(32)
            }
        }
        __syncthreads();
        if (tid == 0) {      // tiny softmax over <= 8 values
            float mx = w8[0];
            for (int i = 1; i < kk; ++i) mx = fmaxf(mx, w8[i]);
            float sum = 0.0f;
            for (int i = 0; i < kk; ++i) { const float e = expf(w8[i] - mx); w8[i] = e; sum += e; }
            const float inv = 1.0f / sum;
            for (int i = 0; i < kk; ++i) w8[i] *= inv;
        }
        __syncthreads();
    }

    float4 msg;
    if (m > 0) {
        float4 a = {0.f, 0.f, 0.f, 0.f};
        for (int i = 0; i < kk; ++i) {
            const float wi = w8[i];
            const float4 xv = *(const float4*)(x + ((size_t)b * NT + jj[i]) * ND + d0);
            a.x = fmaf(wi, xv.x, a.x);
            a.y = fmaf(wi, xv.y, a.y);
            a.z = fmaf(wi, xv.z, a.z);
            a.w = fmaf(wi, xv.w, a.w);
        }
        msg = a;
    } else {
        msg = *(const float4*)(g_mean + b * ND + d0);   // t==0: uniform over all T
    }

    const float om = 1.0f - mix;
    float4 o;
#define GEL(c) { float z = mix * xt.c + om * msg.c;                         \
                 z = fmaf(z, gn.c, bs.c);                                   \
                 o.c = 0.5f * z * (1.0f + erff(z * 0.7071067811865476f)) * scale; }
    GEL(x) GEL(y) GEL(z) GEL(w)
#undef GEL
    *(float4*)(out + (size_t)row * ND + d0) = o;
}

// =========================================================================
extern "C" void kernel_launch(void* const* d_in, const int* in_sizes, int n_in,
                              void* d_out, int out_size)
{
    (void)in_sizes; (void)n_in; (void)out_size;
    const float* x    = (const float*)d_in[0];
    const float* Wq   = (const float*)d_in[1];
    const float* Wk   = (const float*)d_in[2];
    const float* gain = (const float*)d_in[3];
    const float* bias = (const float*)d_in[4];
    const float* lm   = (const float*)d_in[5];
    const float* ls   = (const float*)d_in[6];
    float* out = (float*)d_out;

    xcvt_kernel<<<NB * NT * ND / 4 / 256, 256>>>(x);
    qk_kernel<<<NB * NT / 64, 256>>>(x, Wq, Wk);
    mean1_kernel<<<dim3(8, NB, 16), 256>>>(x);
    simmma_kernel<<<dim3(528, NB), 256>>>();
    mean2_kernel<<<(NB * ND + 255) / 256, 256>>>();
    merge_kernel<<<(NB * NT + 255) / 256, 256>>>();
    finish_kernel<<<NB * NT, 256>>>(x, gain, bias, lm, ls, out);
}

// round 14
// speedup vs baseline: 1.4433x; 1.0012x over previous
#include <cuda_runtime.h>
#include <cuda_bf16.h>
#include <math.h>
#include <stdint.h>

#define NB 2
#define NT 4096
#define ND 1024
#define DH 32
#define KTOP 8
#define TILE 128
#define KC 64            // bf16 K-chunk: 64 elems = 128 bytes/row (SW128)
#define NCH (ND / KC)    // 16 chunks
#define NCPT 12          // candidates kept per tile (screening margin)
#define NCAND 12         // merged candidates per row
#define SIM_STAGE 32768  // A 16KB + B 16KB per stage
#define SIM_SMEM  65536  // 2 stages

// ---------------- scratch (device globals; no allocation) ----------------
__device__ __nv_bfloat16 g_xb[NB * NT * ND];
__device__ float g_q[NB * NT * DH];
__device__ float g_k[NB * NT * DH];
__device__ float g_cv[NB * NT * 32 * NCPT];
__device__ int   g_ci[NB * NT * 32 * NCPT];
__device__ int   g_cand[NB * NT * NCAND];
__device__ int   g_cnt[NB * NT];
__device__ float g_meanp[16 * NB * ND];
__device__ float g_mean[NB * ND];

// ======================= helpers ===========================
__device__ __forceinline__ uint32_t smem_u32(const void* p) {
    uint32_t a;
    asm("{ .reg .u64 t; cvta.to.shared.u64 t, %1; cvt.u32.u64 %0, t; }" : "=r"(a) : "l"(p));
    return a;
}
#define SW128(o) ((o) ^ (((o) >> 3) & 0x70))
#define CP_ASYNC16(dst, src) \
    asm volatile("cp.async.cg.shared.global [%0], [%1], 16;" :: "r"(dst), "l"(src))
#define CP_COMMIT() asm volatile("cp.async.commit_group;" ::: "memory")
#define CP_WAIT(n)  asm volatile("cp.async.wait_group %0;" :: "n"(n) : "memory")

__device__ __forceinline__ void ldmatrix_x4(uint32_t& r0, uint32_t& r1, uint32_t& r2, uint32_t& r3,
                                            uint32_t addr) {
    asm volatile("ldmatrix.sync.aligned.m8n8.x4.shared.b16 {%0,%1,%2,%3}, [%4];"
                 : "=r"(r0), "=r"(r1), "=r"(r2), "=r"(r3) : "r"(addr));
}
__device__ __forceinline__ void mma_bf16(float& c0, float& c1, float& c2, float& c3,
                                         uint32_t a0, uint32_t a1, uint32_t a2, uint32_t a3,
                                         uint32_t b0, uint32_t b1) {
    asm volatile("mma.sync.aligned.m16n8k16.row.col.f32.bf16.bf16.f32 "
                 "{%0,%1,%2,%3}, {%4,%5,%6,%7}, {%8,%9}, {%0,%1,%2,%3};"
                 : "+f"(c0), "+f"(c1), "+f"(c2), "+f"(c3)
                 : "r"(a0), "r"(a1), "r"(a2), "r"(a3), "r"(b0), "r"(b1));
}

// ========================= Kernel: x -> bf16 ============================
__global__ __launch_bounds__(256) void xcvt_kernel(const float* __restrict__ x)
{
    const size_t i = (size_t)blockIdx.x * 256 + threadIdx.x;   // float4 index
    const float4 v = ((const float4*)x)[i];
    __nv_bfloat162* o = (__nv_bfloat162*)g_xb;
    o[2 * i + 0] = __floats2bfloat162_rn(v.x, v.y);
    o[2 * i + 1] = __floats2bfloat162_rn(v.z, v.w);
}

// =============== Kernel: HMMA sim GEMM + per-tile top-12 =============
// One CTA per (tt, jt) pair per batch. 256 threads = 8 warps (2m x 4n),
// warp tile 64x32, mma m16n8k16 bf16, fp32 accum.
// KC=64 (SW128), 2-stage cp.async pipeline in 64KB dynamic smem; 2 CTAs/SM.
__global__ __launch_bounds__(256, 2) void simmma_kernel()
{
    extern __shared__ __align__(128) char sm[];
    const int tid = threadIdx.x;
    const int w = tid >> 5, l = tid & 31;
    const int b = blockIdx.y;

    // decode job -> (tt, jt)
    const int id = blockIdx.x;
    int tt = (int)((sqrtf(8.0f * (float)id + 1.0f) - 1.0f) * 0.5f);
    while ((tt + 1) * (tt + 2) / 2 <= id) ++tt;
    while (tt * (tt + 1) / 2 > id) --tt;
    const int jt = id - tt * (tt + 1) / 2;
    const int t0 = tt * TILE, j0 = jt * TILE;

    const int wm = (w >> 2) * 64;     // warp row offset (0 or 64)
    const int wn = (w & 3) * 32;      // warp col offset

    // ---- swizzled ldmatrix byte offsets (128B rows, SW128) ----
    const int lr8 = l & 7;
    const int lb3 = (l >> 3) & 1;
    const int lb4 = (l >> 4) & 1;
    uint32_t aoff[4], boff[2];
#pragma unroll
    for (int mi = 0; mi < 4; ++mi) {
        const uint32_t row = (uint32_t)(wm + mi * 16 + lr8 + lb3 * 8);
        aoff[mi] = SW128(row * 128 + (uint32_t)lb4 * 16);
    }
#pragma unroll
    for (int n2 = 0; n2 < 2; ++n2) {
        const uint32_t row = (uint32_t)(wn + n2 * 16 + lb4 * 8 + lr8);
        boff[n2] = SW128(row * 128 + (uint32_t)lb3 * 16);
    }

    float acc[4][4][4];
#pragma unroll
    for (int mi = 0; mi < 4; ++mi)
#pragma unroll
        for (int ni = 0; ni < 4; ++ni)
#pragma unroll
            for (int q = 0; q < 4; ++q) acc[mi][ni][q] = 0.0f;

    const __nv_bfloat16* xb = g_xb + (size_t)b * NT * ND;
    const int r  = tid >> 1;              // row 0..127
    const int u0 = (tid & 1) * 4;         // first 16B unit (of 8 per 128B row)
    const uint32_t sb = smem_u32(sm);
    uint32_t so[4];
#pragma unroll
    for (int i = 0; i < 4; ++i) so[i] = SW128((uint32_t)(r * 128 + (u0 + i) * 16));
    const __nv_bfloat16* arow = xb + (size_t)(t0 + r) * ND + u0 * 8;
    const __nv_bfloat16* brow = xb + (size_t)(j0 + r) * ND + u0 * 8;

#define ISSUE(cc, pp) do {                                                      \
    const uint32_t aB_ = sb + (pp) * SIM_STAGE;                                 \
    const __nv_bfloat16* as_ = arow + (cc) * KC;                                \
    const __nv_bfloat16* bs_ = brow + (cc) * KC;                                \
    CP_ASYNC16(aB_ + so[0], as_);           CP_ASYNC16(aB_ + so[1], as_ + 8);   \
    CP_ASYNC16(aB_ + so[2], as_ + 16);      CP_ASYNC16(aB_ + so[3], as_ + 24);  \
    CP_ASYNC16(aB_ + 16384 + so[0], bs_);       CP_ASYNC16(aB_ + 16384 + so[1], bs_ + 8);  \
    CP_ASYNC16(aB_ + 16384 + so[2], bs_ + 16);  CP_ASYNC16(aB_ + 16384 + so[3], bs_ + 24); \
    CP_COMMIT();                                                                \
} while (0)

    ISSUE(0, 0);
#pragma unroll 1
    for (int c = 0; c < NCH; ++c) {
        CP_WAIT(0);
        __syncthreads();                  // chunk c ready; all warps done with c-1
        if (c + 1 < NCH) ISSUE(c + 1, (c + 1) & 1);
        const uint32_t aB = sb + (c & 1) * SIM_STAGE;
        const uint32_t bB = aB + 16384;
#pragma unroll
        for (int ks = 0; ks < 4; ++ks) {
            uint32_t af[4][4], bf[2][4];
#pragma unroll
            for (int mi = 0; mi < 4; ++mi)
                ldmatrix_x4(af[mi][0], af[mi][1], af[mi][2], af[mi][3],
                            aB + (aoff[mi] ^ (ks * 32)));
#pragma unroll
            for (int n2 = 0; n2 < 2; ++n2)
                ldmatrix_x4(bf[n2][0], bf[n2][1], bf[n2][2], bf[n2][3],
                            bB + (boff[n2] ^ (ks * 32)));
#pragma unroll
            for (int mi = 0; mi < 4; ++mi)
#pragma unroll
                for (int ni = 0; ni < 4; ++ni)
                    mma_bf16(acc[mi][ni][0], acc[mi][ni][1], acc[mi][ni][2], acc[mi][ni][3],
                             af[mi][0], af[mi][1], af[mi][2], af[mi][3],
                             bf[ni >> 1][(ni & 1) * 2], bf[ni >> 1][(ni & 1) * 2 + 1]);
        }
    }
#undef ISSUE

    // ---- epilogue: 2 phases x 64 cols; float4 scan with causal clamp ----
    const int g  = l >> 2;
    const int tg = l & 3;
    float* sc = (float*)sm;                 // [128][68] per phase (34816 B)
    float tv[NCPT]; int tj[NCPT];
#pragma unroll
    for (int i = 0; i < NCPT; ++i) { tv[i] = -3.0e38f; tj[i] = 0; }
    const int myt = t0 + tid;               // row this thread scans (tid < 128)

#pragma unroll 1
    for (int ph = 0; ph < 2; ++ph) {
        __syncthreads();                    // prior reads done
        if (((w & 3) >> 1) == ph) {
            const int cb = ((w & 3) & 1) * 32;
#pragma unroll
            for (int mi = 0; mi < 4; ++mi)
#pragma unroll
                for (int ni = 0; ni < 4; ++ni) {
                    const int colw = cb + ni * 8 + tg * 2;
                    float* p0 = sc + (wm + mi * 16 + g) * 68 + colw;
                    float* p1 = sc + (wm + mi * 16 + g + 8) * 68 + colw;
                    p0[0] = acc[mi][ni][0]; p0[1] = acc[mi][ni][1];
                    p1[0] = acc[mi][ni][2]; p1[1] = acc[mi][ni][3];
                }
        }
        __syncthreads();
        if (tid < 128) {
            const float4* rowp = (const float4*)(sc + tid * 68);
            const int jb = j0 + ph * 64;
            const int limit = myt - jb;     // columns [0, limit) are causal
            if (limit > 0) {
                const int nv4 = limit >= 64 ? 16 : ((limit + 3) >> 2);
                float thr = tv[NCPT - 1];
#pragma unroll 1
                for (int v4 = 0; v4 < nv4; ++v4) {
                    const float4 vv = rowp[v4];
                    const float m01 = fmaxf(vv.x, vv.y);
                    const float m23 = fmaxf(vv.z, vv.w);
                    if (fmaxf(m01, m23) > thr) {
                        const int jb4 = jb + v4 * 4;
                        const float va[4] = {vv.x, vv.y, vv.z, vv.w};
#pragma unroll
                        for (int e = 0; e < 4; ++e) {
                            const float v = va[e];
                            const int   j = jb4 + e;
                            if (v > thr && j < myt) {
                                tv[NCPT - 1] = v; tj[NCPT - 1] = j;
#pragma unroll
                                for (int q = NCPT - 1; q > 0; --q) {
                                    if (tv[q] > tv[q - 1]) {
                                        const float tf = tv[q]; tv[q] = tv[q - 1]; tv[q - 1] = tf;
                                        const int   ii = tj[q]; tj[q] = tj[q - 1]; tj[q - 1] = ii;
                                    }
                                }
                                thr = tv[NCPT - 1];
                            }
                        }
                    }
                }
            }
        }
    }

    if (tid < 128) {
        const size_t base = ((size_t)(b * NT + myt) * 32 + jt) * NCPT;
#pragma unroll
        for (int i = 0; i < NCPT; ++i) { g_cv[base + i] = tv[i]; g_ci[base + i] = tj[i]; }
    }
}

// == Kernel: merge per-tile lists -> top-12 candidates (+ mean reduce) ==
__global__ void merge_kernel()
{
    const int row = blockIdx.x * blockDim.x + threadIdx.x;
    if (row < NB * ND) {        // final mean reduction (2048 entries)
        const int b = row / ND, d = row % ND;
        float s = 0.0f;
        for (int z = 0; z < 16; ++z) s += g_meanp[((size_t)z * NB + b) * ND + d];
        g_mean[row] = s * (1.0f / (float)NT);
    }
    if (row >= NB * NT) return;
    const int t  = row & (NT - 1);
    const int nl = (t >> 7) + 1;
    float bv[NCAND]; int bi[NCAND];
    for (int i = 0; i < NCAND; ++i) { bv[i] = -3.0e38f; bi[i] = 0; }
    for (int l = 0; l < nl; ++l) {
        const size_t base = ((size_t)row * 32 + l) * NCPT;
        for (int i = 0; i < NCPT; ++i) {
            const float v = g_cv[base + i];
            if (v <= bv[NCAND - 1]) break;          // lists sorted desc
            const int j = g_ci[base + i];
            int pos = NCAND - 1;
            while (pos > 0 && bv[pos - 1] < v) {
                bv[pos] = bv[pos - 1]; bi[pos] = bi[pos - 1]; --pos;
            }
            bv[pos] = v; bi[pos] = j;
        }
    }
    int m = 0;
    for (int i = 0; i < NCAND; ++i) {
        if (bv[i] > -1.0e30f) { g_cand[(size_t)row * NCAND + i] = bi[i]; ++m; }
    }
    g_cnt[row] = m;
}

// ===================== Kernel: q/k projection ===========================
__global__ __launch_bounds__(256) void qk_kernel(const float* __restrict__ x,
                                                 const float* __restrict__ Wq,
                                                 const float* __restrict__ Wk)
{
    const int row0 = blockIdx.x * 64;
    __shared__ float xs[16][64];
    __shared__ float ws[16][64];
    const int tid = threadIdx.x;
    const int ty = tid >> 4, tx = tid & 15;
    const int lr = tid >> 2;
    const int lk = (tid & 3) * 4;
    float acc[4][4];
#pragma unroll
    for (int i = 0; i < 4; ++i)
#pragma unroll
        for (int j = 0; j < 4; ++j) acc[i][j] = 0.0f;

    const float* Wrow = (lr < 32) ? (Wq + (size_t)lr * ND) : (Wk + (size_t)(lr - 32) * ND);
    for (int kd = 0; kd < ND; kd += 16) {
        const float4 xv = *(const float4*)(x + (size_t)(row0 + lr) * ND + kd + lk);
        const float4 wv = *(const float4*)(Wrow + kd + lk);
        __syncthreads();
        xs[lk + 0][lr] = xv.x; xs[lk + 1][lr] = xv.y; xs[lk + 2][lr] = xv.z; xs[lk + 3][lr] = xv.w;
        ws[lk + 0][lr] = wv.x; ws[lk + 1][lr] = wv.y; ws[lk + 2][lr] = wv.z; ws[lk + 3][lr] = wv.w;
        __syncthreads();
#pragma unroll
        for (int k = 0; k < 16; ++k) {
            const float4 a  = *(const float4*)&xs[k][4 * ty];
            const float4 w4 = *(const float4*)&ws[k][4 * tx];
            const float ar[4] = {a.x, a.y, a.z, a.w};
            const float br[4] = {w4.x, w4.y, w4.z, w4.w};
#pragma unroll
            for (int i = 0; i < 4; ++i)
#pragma unroll
                for (int j = 0; j < 4; ++j)
                    acc[i][j] = fmaf(ar[i], br[j], acc[i][j]);
        }
    }
#pragma unroll
    for (int i = 0; i < 4; ++i) {
        const int rw = row0 + 4 * ty + i;
#pragma unroll
        for (int j = 0; j < 4; ++j) {
            const int h = 4 * tx + j;
            if (h < 32) g_q[(size_t)rw * DH + h] = acc[i][j];
            else        g_k[(size_t)rw * DH + (h - 32)] = acc[i][j];
        }
    }
}

// ============== Kernel: mean partials (deterministic) ===================
__global__ void mean1_kernel(const float* __restrict__ x)
{
    const int b = blockIdx.y, z = blockIdx.z;
    const int lane = threadIdx.x & 31, g = threadIdx.x >> 5;
    const int c4 = blockIdx.x * 32 + lane;
    const float* xb = x + (size_t)b * NT * ND;
    float4 acc = {0.f, 0.f, 0.f, 0.f};
    for (int r = z * 256 + g; r < z * 256 + 256; r += 8) {
        const float4 v = *(const float4*)(xb + (size_t)r * ND + 4 * c4);
        acc.x += v.x; acc.y += v.y; acc.z += v.z; acc.w += v.w;
    }
    __shared__ float4 red[8][32];
    red[g][lane] = acc;
    __syncthreads();
    if (g == 0) {
        float4 sm = red[0][lane];
        for (int q = 1; q < 8; ++q) {
            const float4 v = red[q][lane];
            sm.x += v.x; sm.y += v.y; sm.z += v.z; sm.w += v.w;
        }
        *(float4*)(g_meanp + ((size_t)z * NB + b) * ND + 4 * c4) = sm;
    }
}

// ====== Kernel: fused exact fp32 re-rank + scores/softmax/msg/GELU ======
__global__ __launch_bounds__(256) void finish_kernel(const float* __restrict__ x,
                                                     const float* __restrict__ gain,
                                                     const float* __restrict__ bias,
                                                     const float* __restrict__ p_lm,
                                                     const float* __restrict__ p_ls,
                                                     float* __restrict__ out)
{
    const int row = blockIdx.x;
    const int b = row >> 12;
    const int t = row & (NT - 1);
    const int tid = threadIdx.x, wid = tid >> 5, lane = tid & 31;

    const float mix   = 1.0f / (1.0f + expf(-p_lm[0]));
    const float scale = log1pf(expf(p_ls[0])) + 0.01f;

    const int d0 = 4 * tid;
    const float4 xt = *(const float4*)(x + (size_t)row * ND + d0);
    const float4 gn = *(const float4*)(gain + d0);
    const float4 bs = *(const float4*)(bias + d0);

    __shared__ float sval[NCAND];
    __shared__ float sqk[NCAND];
    __shared__ int   scand[NCAND];
    __shared__ float w8[KTOP];
    __shared__ int   jj[KTOP];

    const int m  = g_cnt[row];
    const int kk = m < KTOP ? m : KTOP;

    if (m > 0) {
        if (tid < m) scand[tid] = g_cand[(size_t)row * NCAND + tid];
        __syncthreads();

        const float4* qa = (const float4*)(x + (size_t)(b * NT + t) * ND);
        const float qh = g_q[(size_t)row * DH + lane];
#pragma unroll 1
        for (int cc = wid; cc < m; cc += 8) {
            const int j = scand[cc];
            const float4* ka = (const float4*)(x + (size_t)(b * NT + j) * ND);
            float s = 0.0f;
#pragma unroll
            for (int i = 0; i < 8; ++i) {
                const float4 q4 = qa[i * 32 + lane];
                const float4 k4 = ka[i * 32 + lane];
                s = fmaf(q4.x, k4.x, s); s = fmaf(q4.y, k4.y, s);
                s = fmaf(q4.z, k4.z, s); s = fmaf(q4.w, k4.w, s);
            }
            float s2 = qh * g_k[((size_t)b * NT + j) * DH + lane];
#pragma unroll
            for (int o = 16; o > 0; o >>= 1) {
                s  += __shfl_xor_sync(0xffffffffu, s, o);
                s2 += __shfl_xor_sync(0xffffffffu, s2, o);
            }
            if (lane == 0) { sval[cc] = s; sqk[cc] = s2; }
        }
        __syncthreads();

        if (tid < m) {
            const float v = sval[tid];
            int rank = 0;
#pragma unroll 1
            for (int i = 0; i < m; ++i) {
                const float u = sval[i];
                rank += (u > v) || (u == v && i < tid);
            }
            if (rank < kk) {
                jj[rank] = scand[tid];
                w8[rank] = sqk[tid] * 0.17677669529663687f;   // 1/sqrt(32)
            }
        }
        __syncthreads();
        if (tid == 0) {
            float mx = w8[0];
            for (int i = 1; i < kk; ++i) mx = fmaxf(mx, w8[i]);
            float sum = 0.0f;
            for (int i = 0; i < kk; ++i) { const float e = expf(w8[i] - mx); w8[i] = e; sum += e; }
            const float inv = 1.0f / sum;
            for (int i = 0; i < kk; ++i) w8[i] *= inv;
        }
        __syncthreads();
    }

    float4 msg;
    if (m > 0) {
        float4 a = {0.f, 0.f, 0.f, 0.f};
        for (int i = 0; i < kk; ++i) {
            const float wi = w8[i];
            const float4 xv = *(const float4*)(x + ((size_t)b * NT + jj[i]) * ND + d0);
            a.x = fmaf(wi, xv.x, a.x);
            a.y = fmaf(wi, xv.y, a.y);
            a.z = fmaf(wi, xv.z, a.z);
            a.w = fmaf(wi, xv.w, a.w);
        }
        msg = a;
    } else {
        msg = *(const float4*)(g_mean + b * ND + d0);   // t==0: uniform over all T
    }

    const float om = 1.0f - mix;
    float4 o;
#define GEL(c) { float z = mix * xt.c + om * msg.c;                         \
                 z = fmaf(z, gn.c, bs.c);                                   \
                 o.c = 0.5f * z * (1.0f + erff(z * 0.7071067811865476f)) * scale; }
    GEL(x) GEL(y) GEL(z) GEL(w)
#undef GEL
    *(float4*)(out + (size_t)row * ND + d0) = o;
}

// =========================================================================
extern "C" void kernel_launch(void* const* d_in, const int* in_sizes, int n_in,
                              void* d_out, int out_size)
{
    (void)in_sizes; (void)n_in; (void)out_size;
    const float* x    = (const float*)d_in[0];
    const float* Wq   = (const float*)d_in[1];
    const float* Wk   = (const float*)d_in[2];
    const float* gain = (const float*)d_in[3];
    const float* bias = (const float*)d_in[4];
    const float* lm   = (const float*)d_in[5];
    const float* ls   = (const float*)d_in[6];
    float* out = (float*)d_out;

    cudaFuncSetAttribute(simmma_kernel, cudaFuncAttributeMaxDynamicSharedMemorySize, SIM_SMEM);

    xcvt_kernel<<<NB * NT * ND / 4 / 256, 256>>>(x);
    qk_kernel<<<NB * NT / 64, 256>>>(x, Wq, Wk);
    mean1_kernel<<<dim3(8, NB, 16), 256>>>(x);
    simmma_kernel<<<dim3(528, NB), 256, SIM_SMEM>>>();
    merge_kernel<<<(NB * NT + 255) / 256, 256>>>();
    finish_kernel<<<NB * NT, 256>>>(x, gain, bias, lm, ls, out);
}